// round 1
// baseline (speedup 1.0000x reference)
#include <cuda_runtime.h>
#include <math.h>

// Problem constants (fixed by the reference: N=4, n=2048, d=1024)
#define NB   4
#define SEQ  2048
#define DIM  1024

#define BM 128
#define BN 128
#define BK 8

// Scratch buffers (allocation-free rule: __device__ globals)
__device__ float g_q  [(long long)NB * SEQ * DIM];   // 32 MB
__device__ float g_s  [(long long)NB * SEQ * SEQ];   // 64 MB (scores -> probs in place)
__device__ float g_att[(long long)NB * SEQ * DIM];   // 32 MB

// ---------------------------------------------------------------------------
// Tiled SGEMM:  C = A * op(B)
//   BT=true :  B is [N,K] row-major, C[i,j] = sum_k A[i,k] * B[j,k]   (A·Bᵀ)
//   BT=false:  B is [K,N] row-major, C[i,j] = sum_k A[i,k] * B[k,j]   (A·B)
// A is [M,K] row-major. M%128==0, N%128==0, K%8==0 (all shapes here comply).
// grid.z = batch, with element strides sA/sB/sC.
// ---------------------------------------------------------------------------
template <bool BT>
__global__ __launch_bounds__(256, 2)
void sgemm_kernel(const float* __restrict__ A, const float* __restrict__ B,
                  float* __restrict__ C, int M, int N, int K,
                  long long sA, long long sB, long long sC)
{
    A += (long long)blockIdx.z * sA;
    B += (long long)blockIdx.z * sB;
    C += (long long)blockIdx.z * sC;

    __shared__ float As[BK][BM + 4];
    __shared__ float Bs[BK][BN + 4];

    const int tid  = threadIdx.x;
    const int row0 = blockIdx.y * BM;
    const int col0 = blockIdx.x * BN;

    // A tile loader: 128 rows x 8 cols; thread t -> row t/2, 4 cols at (t&1)*4
    const int a_row = tid >> 1;
    const int a_col = (tid & 1) << 2;
    // NN B tile loader: 8 rows x 128 cols; thread t -> row t/32, 4 cols at (t&31)*4
    const int bnn_row = tid >> 5;
    const int bnn_col = (tid & 31) << 2;

    const int tx = tid & 15;   // micro-tile col group
    const int ty = tid >> 4;   // micro-tile row group

    float acc[8][8] = {};

    const float* Ag = A + (long long)(row0 + a_row) * K + a_col;
    const float* Bg;
    if (BT) Bg = B + (long long)(col0 + a_row) * K + a_col;
    else    Bg = B + (long long)bnn_row * N + col0 + bnn_col;

    for (int k0 = 0; k0 < K; k0 += BK) {
        float4 av = *(const float4*)(Ag + k0);
        As[a_col + 0][a_row] = av.x;
        As[a_col + 1][a_row] = av.y;
        As[a_col + 2][a_row] = av.z;
        As[a_col + 3][a_row] = av.w;

        if (BT) {
            float4 bv = *(const float4*)(Bg + k0);
            Bs[a_col + 0][a_row] = bv.x;
            Bs[a_col + 1][a_row] = bv.y;
            Bs[a_col + 2][a_row] = bv.z;
            Bs[a_col + 3][a_row] = bv.w;
        } else {
            float4 bv = *(const float4*)(Bg + (long long)k0 * N);
            *(float4*)&Bs[bnn_row][bnn_col] = bv;
        }
        __syncthreads();

        #pragma unroll
        for (int kk = 0; kk < BK; kk++) {
            float ra[8], rb[8];
            *(float4*)&ra[0] = *(const float4*)&As[kk][ty * 8];
            *(float4*)&ra[4] = *(const float4*)&As[kk][ty * 8 + 4];
            *(float4*)&rb[0] = *(const float4*)&Bs[kk][tx * 8];
            *(float4*)&rb[4] = *(const float4*)&Bs[kk][tx * 8 + 4];
            #pragma unroll
            for (int i = 0; i < 8; i++)
                #pragma unroll
                for (int j = 0; j < 8; j++)
                    acc[i][j] = fmaf(ra[i], rb[j], acc[i][j]);
        }
        __syncthreads();
    }

    #pragma unroll
    for (int i = 0; i < 8; i++) {
        float* cp = C + (long long)(row0 + ty * 8 + i) * N + col0 + tx * 8;
        *(float4*)(cp)     = make_float4(acc[i][0], acc[i][1], acc[i][2], acc[i][3]);
        *(float4*)(cp + 4) = make_float4(acc[i][4], acc[i][5], acc[i][6], acc[i][7]);
    }
}

// ---------------------------------------------------------------------------
// Fused scale + mask + softmax, in place over one row of S (length SEQ=2048).
// One block of 256 threads per row; 8 elements/thread via float4/int4.
// s' = mask ? s/32 : -1e30 ; softmax over row.
// ---------------------------------------------------------------------------
__global__ __launch_bounds__(256)
void softmax_mask_kernel(float* __restrict__ S, const int* __restrict__ mask)
{
    const long long row = blockIdx.x;
    float* s      = S    + row * SEQ;
    const int* m  = mask + row * SEQ;
    const int tid = threadIdx.x;
    const float scale = 0.03125f; // 1/sqrt(1024) = 1/32 exactly

    float v[8];
    #pragma unroll
    for (int u = 0; u < 2; u++) {
        const int base = u * 1024 + tid * 4;
        float4 sv = *(const float4*)(s + base);
        int4   mv = *(const int4*)(m + base);
        v[u*4 + 0] = mv.x ? sv.x * scale : -1e30f;
        v[u*4 + 1] = mv.y ? sv.y * scale : -1e30f;
        v[u*4 + 2] = mv.z ? sv.z * scale : -1e30f;
        v[u*4 + 3] = mv.w ? sv.w * scale : -1e30f;
    }

    __shared__ float red[8];

    // row max
    float mx = v[0];
    #pragma unroll
    for (int i = 1; i < 8; i++) mx = fmaxf(mx, v[i]);
    #pragma unroll
    for (int o = 16; o > 0; o >>= 1) mx = fmaxf(mx, __shfl_xor_sync(0xffffffffu, mx, o));
    if ((tid & 31) == 0) red[tid >> 5] = mx;
    __syncthreads();
    mx = red[0];
    #pragma unroll
    for (int w = 1; w < 8; w++) mx = fmaxf(mx, red[w]);
    __syncthreads();

    // exp + row sum
    float sum = 0.f;
    #pragma unroll
    for (int i = 0; i < 8; i++) { v[i] = expf(v[i] - mx); sum += v[i]; }
    #pragma unroll
    for (int o = 16; o > 0; o >>= 1) sum += __shfl_xor_sync(0xffffffffu, sum, o);
    if ((tid & 31) == 0) red[tid >> 5] = sum;
    __syncthreads();
    sum = red[0];
    #pragma unroll
    for (int w = 1; w < 8; w++) sum += red[w];

    const float inv = 1.0f / sum;
    #pragma unroll
    for (int u = 0; u < 2; u++) {
        const int base = u * 1024 + tid * 4;
        *(float4*)(s + base) = make_float4(v[u*4+0]*inv, v[u*4+1]*inv,
                                           v[u*4+2]*inv, v[u*4+3]*inv);
    }
}

// ---------------------------------------------------------------------------
// Launch: q = x·Wqkᵀ ; S = q·xᵀ (batched) ; softmax(mask, S/32) ;
//         att = P·x (batched) ; out = att·Wvcᵀ
// ---------------------------------------------------------------------------
extern "C" void kernel_launch(void* const* d_in, const int* in_sizes, int n_in,
                              void* d_out, int out_size)
{
    const float* x    = (const float*)d_in[0];
    const int*   mask = (const int*)  d_in[1];
    const float* Wqk  = (const float*)d_in[2];
    const float* Wvc  = (const float*)d_in[3];
    float*       out  = (float*)d_out;

    float *q, *s, *att;
    cudaGetSymbolAddress((void**)&q,   g_q);
    cudaGetSymbolAddress((void**)&s,   g_s);
    cudaGetSymbolAddress((void**)&att, g_att);

    const long long sXD = (long long)SEQ * DIM;   // per-batch stride of x/q/att
    const long long sSS = (long long)SEQ * SEQ;   // per-batch stride of S

    dim3 blk(256);

    // 1) q = x @ Wqk^T : [8192,1024] x [1024,1024]^T
    sgemm_kernel<true><<<dim3(DIM / BN, (NB * SEQ) / BM, 1), blk>>>(
        x, Wqk, q, NB * SEQ, DIM, DIM, 0, 0, 0);

    // 2) S_b = q_b @ x_b^T : [2048,1024] x [2048,1024]^T, batched over 4
    sgemm_kernel<true><<<dim3(SEQ / BN, SEQ / BM, NB), blk>>>(
        q, x, s, SEQ, SEQ, DIM, sXD, sXD, sSS);

    // 3) P = softmax(mask ? S/32 : -inf), in place
    softmax_mask_kernel<<<NB * SEQ, 256>>>(s, mask);

    // 4) att_b = P_b @ x_b : [2048,2048] x [2048,1024], batched over 4
    sgemm_kernel<false><<<dim3(DIM / BN, SEQ / BM, NB), blk>>>(
        s, x, att, SEQ, DIM, SEQ, sSS, sXD, sXD);

    // 5) out = att @ Wvc^T : [8192,1024] x [1024,1024]^T
    sgemm_kernel<true><<<dim3(DIM / BN, (NB * SEQ) / BM, 1), blk>>>(
        att, Wvc, out, NB * SEQ, DIM, DIM, 0, 0, 0);
}

// round 3
// speedup vs baseline: 2.5426x; 2.5426x over previous
#include <cuda_runtime.h>
#include <cuda_bf16.h>
#include <math.h>
#include <stdint.h>

// Problem constants: N=4, n=2048, d=1024
#define NB   4
#define SEQ  2048
#define DIM  1024

// ---------------------------------------------------------------------------
// Scratch (__device__ globals; allocation-free rule)
// ---------------------------------------------------------------------------
__device__ __nv_bfloat16 g_xh [(size_t)NB*SEQ*DIM];
__device__ __nv_bfloat16 g_xl [(size_t)NB*SEQ*DIM];
__device__ __nv_bfloat16 g_xth[(size_t)NB*DIM*SEQ];   // x^T per batch [DIM,SEQ]
__device__ __nv_bfloat16 g_xtl[(size_t)NB*DIM*SEQ];
__device__ __nv_bfloat16 g_wqh[(size_t)DIM*DIM];
__device__ __nv_bfloat16 g_wql[(size_t)DIM*DIM];
__device__ __nv_bfloat16 g_wvh[(size_t)DIM*DIM];
__device__ __nv_bfloat16 g_wvl[(size_t)DIM*DIM];
__device__ __nv_bfloat16 g_qh [(size_t)NB*SEQ*DIM];
__device__ __nv_bfloat16 g_ql [(size_t)NB*SEQ*DIM];
__device__ float         g_s  [(size_t)NB*SEQ*SEQ];
__device__ __nv_bfloat16 g_ph [(size_t)NB*SEQ*SEQ];
__device__ __nv_bfloat16 g_pl [(size_t)NB*SEQ*SEQ];
__device__ __nv_bfloat16 g_ah [(size_t)NB*SEQ*DIM];
__device__ __nv_bfloat16 g_al [(size_t)NB*SEQ*DIM];

// ---------------------------------------------------------------------------
// Baseline-PTX helpers (compute_100-safe: ldmatrix / mma.sync / cp.async)
// ---------------------------------------------------------------------------
__device__ __forceinline__ uint32_t smem_u32(const void* p) {
    uint32_t a;
    asm("{ .reg .u64 t; cvta.to.shared.u64 t, %1; cvt.u32.u64 %0, t; }" : "=r"(a) : "l"(p));
    return a;
}
__device__ __forceinline__ void ldsm4(uint32_t* r, uint32_t a) {
    asm volatile("ldmatrix.sync.aligned.m8n8.x4.shared.b16 {%0,%1,%2,%3}, [%4];"
        : "=r"(r[0]), "=r"(r[1]), "=r"(r[2]), "=r"(r[3]) : "r"(a));
}
__device__ __forceinline__ void mma16816(float* c, const uint32_t* a, const uint32_t* b) {
    asm volatile("mma.sync.aligned.m16n8k16.row.col.f32.bf16.bf16.f32 "
        "{%0,%1,%2,%3}, {%4,%5,%6,%7}, {%8,%9}, {%0,%1,%2,%3};"
        : "+f"(c[0]), "+f"(c[1]), "+f"(c[2]), "+f"(c[3])
        : "r"(a[0]), "r"(a[1]), "r"(a[2]), "r"(a[3]), "r"(b[0]), "r"(b[1]));
}
#define CP_ASYNC16(so, gp) \
    asm volatile("cp.async.cg.shared.global [%0], [%1], 16;" :: "r"(so), "l"(gp) : "memory")
#define CP_COMMIT() asm volatile("cp.async.commit_group;" ::: "memory")
#define CP_WAIT2()  asm volatile("cp.async.wait_group 2;" ::: "memory")

// SW64-style swizzle for 64B rows: XOR 16B-column bits [4:5] with row bits [7:8]
#define SWZ64(o) ((o) ^ (((o) >> 3) & 0x30))

// ---------------------------------------------------------------------------
// Split-bf16 NT GEMM on legacy tensor cores:
//   C[M,N] = A[M,K] · B[N,K]^T,  C ≈ Ah·Bh + Ah·Bl + Al·Bh  (fp32 accum)
// MODE 0: write fp32 C. MODE 1: write split (Ch bf16 hi, Cl bf16 lo).
// 128x128 CTA tile, BK=32, 3-stage cp.async pipeline, 8 warps (4m x 2n).
// ---------------------------------------------------------------------------
#define TILE_B  8192            // 128 rows x 64 bytes
#define STAGE_B 32768           // Ah, Al, Bh, Bl tiles
#define NSTAGE  3
#define GEMM_SMEM (NSTAGE * STAGE_B)

template <int MODE>
__global__ __launch_bounds__(256, 1)
void mma_gemm_nt(const __nv_bfloat16* __restrict__ Ah, const __nv_bfloat16* __restrict__ Al,
                 const __nv_bfloat16* __restrict__ Bh, const __nv_bfloat16* __restrict__ Bl,
                 float* __restrict__ Cf, __nv_bfloat16* __restrict__ Ch,
                 __nv_bfloat16* __restrict__ Cl,
                 int K, int ldc, long long sA, long long sB, long long sC)
{
    extern __shared__ char smraw[];
    const uint32_t base = smem_u32(smraw);

    const int tid  = threadIdx.x;
    const int wid  = tid >> 5;
    const int lid  = tid & 31;
    const int bz   = blockIdx.z;
    const int row0 = blockIdx.y * 128;
    const int col0 = blockIdx.x * 128;

    const int warp_m = wid >> 1;          // 0..3 -> 32-row slab
    const int warp_n = wid & 1;           // 0..1 -> 64-col slab

    const __nv_bfloat16* src[4] = { Ah + (size_t)bz * sA, Al + (size_t)bz * sA,
                                    Bh + (size_t)bz * sB, Bl + (size_t)bz * sB };
    const int rb[4] = { row0, row0, col0, col0 };

    const int nCh = K >> 5;               // chunks of 32

    // loader indexing: id = tid + g*256 in [0,2048): tile=id>>9, r=(id&511)>>2, c16=id&3
    auto issue_stage = [&](int i) {
        const uint32_t stage = base + (uint32_t)(i % NSTAGE) * STAGE_B;
        const int k0 = i << 5;
        #pragma unroll
        for (int g = 0; g < 8; g++) {
            const int id   = tid + g * 256;
            const int tile = id >> 9;
            const int rem  = id & 511;
            const int r    = rem >> 2;
            const int c16  = rem & 3;
            const __nv_bfloat16* gp = src[tile] + (size_t)(rb[tile] + r) * K + k0 + c16 * 8;
            const uint32_t so = stage + (uint32_t)tile * TILE_B + SWZ64(r * 64 + c16 * 16);
            CP_ASYNC16(so, gp);
        }
    };

    float acc[2][8][4];
    #pragma unroll
    for (int mt = 0; mt < 2; mt++)
        #pragma unroll
        for (int nt = 0; nt < 8; nt++)
            #pragma unroll
            for (int e = 0; e < 4; e++) acc[mt][nt][e] = 0.f;

    // prologue: stages 0,1
    issue_stage(0); CP_COMMIT();
    if (nCh > 1) { issue_stage(1); }
    CP_COMMIT();

    // ldmatrix lane addressing (byte offsets within a tile, before swizzle)
    // A: row = m0 + mt*16 + ((l>>3)&1)*8 + (l&7), c16 = 2*s + (l>>4)
    const int a_r_lane = ((lid >> 3) & 1) * 8 + (lid & 7);
    const int a_c_lane = lid >> 4;
    // B: row = n0 + nt16*16 + (l>>4)*8 + (l&7), c16 = 2*s + ((l>>3)&1)
    const int b_r_lane = (lid >> 4) * 8 + (lid & 7);
    const int b_c_lane = (lid >> 3) & 1;

    for (int i = 0; i < nCh; i++) {
        if (i + 2 < nCh) issue_stage(i + 2);
        CP_COMMIT();
        CP_WAIT2();
        __syncthreads();

        const uint32_t stage = base + (uint32_t)(i % NSTAGE) * STAGE_B;
        const uint32_t sAh = stage;
        const uint32_t sAl = stage + TILE_B;
        const uint32_t sBh = stage + 2 * TILE_B;
        const uint32_t sBl = stage + 3 * TILE_B;

        #pragma unroll
        for (int s = 0; s < 2; s++) {       // two k16 steps per 32-chunk
            uint32_t afh[2][4], afl[2][4], bfh[4][4], bfl[4][4];
            #pragma unroll
            for (int mt = 0; mt < 2; mt++) {
                const int row = warp_m * 32 + mt * 16 + a_r_lane;
                const int off = SWZ64(row * 64 + (2 * s + a_c_lane) * 16);
                ldsm4(afh[mt], sAh + off);
                ldsm4(afl[mt], sAl + off);
            }
            #pragma unroll
            for (int nt = 0; nt < 4; nt++) {
                const int row = warp_n * 64 + nt * 16 + b_r_lane;
                const int off = SWZ64(row * 64 + (2 * s + b_c_lane) * 16);
                ldsm4(bfh[nt], sBh + off);
                ldsm4(bfl[nt], sBl + off);
            }
            // combos outermost: consecutive MMAs hit different accumulators
            #pragma unroll
            for (int mt = 0; mt < 2; mt++)
                #pragma unroll
                for (int nt = 0; nt < 8; nt++)
                    mma16816(acc[mt][nt], afh[mt], &bfh[nt >> 1][(nt & 1) * 2]);
            #pragma unroll
            for (int mt = 0; mt < 2; mt++)
                #pragma unroll
                for (int nt = 0; nt < 8; nt++)
                    mma16816(acc[mt][nt], afh[mt], &bfl[nt >> 1][(nt & 1) * 2]);
            #pragma unroll
            for (int mt = 0; mt < 2; mt++)
                #pragma unroll
                for (int nt = 0; nt < 8; nt++)
                    mma16816(acc[mt][nt], afl[mt], &bfh[nt >> 1][(nt & 1) * 2]);
        }
        __syncthreads();
    }

    // Epilogue. Accum layout per mma tile: c0,c1 -> row l>>2, cols (l&3)*2, +1;
    // c2,c3 -> row (l>>2)+8.
    const int er = lid >> 2;
    const int ec = (lid & 3) * 2;
    #pragma unroll
    for (int mt = 0; mt < 2; mt++) {
        #pragma unroll
        for (int nt = 0; nt < 8; nt++) {
            const int r_g = row0 + warp_m * 32 + mt * 16 + er;
            const int c_g = col0 + warp_n * 64 + nt * 8 + ec;
            if (MODE == 0) {
                float* cp0 = Cf + (size_t)bz * sC + (size_t)r_g * ldc + c_g;
                float* cp1 = cp0 + (size_t)8 * ldc;
                cp0[0] = acc[mt][nt][0]; cp0[1] = acc[mt][nt][1];
                cp1[0] = acc[mt][nt][2]; cp1[1] = acc[mt][nt][3];
            } else {
                const size_t o0 = (size_t)bz * sC + (size_t)r_g * ldc + c_g;
                const size_t o1 = o0 + (size_t)8 * ldc;
                #pragma unroll
                for (int h = 0; h < 2; h++) {
                    const float v0 = acc[mt][nt][h * 2];
                    const float v1 = acc[mt][nt][h * 2 + 1];
                    const __nv_bfloat16 h0 = __float2bfloat16(v0);
                    const __nv_bfloat16 h1 = __float2bfloat16(v1);
                    __nv_bfloat162 hh; hh.x = h0; hh.y = h1;
                    __nv_bfloat162 ll;
                    ll.x = __float2bfloat16(v0 - __bfloat162float(h0));
                    ll.y = __float2bfloat16(v1 - __bfloat162float(h1));
                    const size_t o = h ? o1 : o0;
                    *(__nv_bfloat162*)(Ch + o) = hh;
                    *(__nv_bfloat162*)(Cl + o) = ll;
                }
            }
        }
    }
}

// ---------------------------------------------------------------------------
// fp32 -> (bf16 hi, bf16 lo) elementwise split
// ---------------------------------------------------------------------------
__global__ __launch_bounds__(256)
void split_kernel(const float* __restrict__ s, __nv_bfloat16* __restrict__ h,
                  __nv_bfloat16* __restrict__ l, int n4)
{
    const int i = blockIdx.x * blockDim.x + threadIdx.x;
    if (i >= n4) return;
    const float4 v = ((const float4*)s)[i];
    __nv_bfloat16 h0 = __float2bfloat16(v.x), h1 = __float2bfloat16(v.y);
    __nv_bfloat16 h2 = __float2bfloat16(v.z), h3 = __float2bfloat16(v.w);
    __nv_bfloat162 a, b, c, d;
    a.x = h0; a.y = h1; b.x = h2; b.y = h3;
    c.x = __float2bfloat16(v.x - __bfloat162float(h0));
    c.y = __float2bfloat16(v.y - __bfloat162float(h1));
    d.x = __float2bfloat16(v.z - __bfloat162float(h2));
    d.y = __float2bfloat16(v.w - __bfloat162float(h3));
    *(__nv_bfloat162*)(h + (size_t)i * 4)     = a;
    *(__nv_bfloat162*)(h + (size_t)i * 4 + 2) = b;
    *(__nv_bfloat162*)(l + (size_t)i * 4)     = c;
    *(__nv_bfloat162*)(l + (size_t)i * 4 + 2) = d;
}

// ---------------------------------------------------------------------------
// x [NB,SEQ,DIM] -> xT [NB,DIM,SEQ], split into hi/lo bf16
// ---------------------------------------------------------------------------
__global__ __launch_bounds__(256)
void transpose_split_kernel(const float* __restrict__ x,
                            __nv_bfloat16* __restrict__ th, __nv_bfloat16* __restrict__ tl)
{
    __shared__ float t[32][33];
    const int b  = blockIdx.z;
    const int d0 = blockIdx.x * 32;
    const int k0 = blockIdx.y * 32;
    const int tx = threadIdx.x & 31;
    const int ty = threadIdx.x >> 5;
    #pragma unroll
    for (int j = 0; j < 32; j += 8)
        t[ty + j][tx] = x[(size_t)b * SEQ * DIM + (size_t)(k0 + ty + j) * DIM + d0 + tx];
    __syncthreads();
    #pragma unroll
    for (int j = 0; j < 32; j += 8) {
        const float v = t[tx][ty + j];
        const __nv_bfloat16 hi = __float2bfloat16(v);
        const size_t off = (size_t)b * DIM * SEQ + (size_t)(d0 + ty + j) * SEQ + k0 + tx;
        th[off] = hi;
        tl[off] = __float2bfloat16(v - __bfloat162float(hi));
    }
}

// ---------------------------------------------------------------------------
// scale + mask + softmax; outputs split bf16 probabilities
// ---------------------------------------------------------------------------
__global__ __launch_bounds__(256)
void softmax_mask_split(const float* __restrict__ S, const int* __restrict__ mask,
                        __nv_bfloat16* __restrict__ Ph, __nv_bfloat16* __restrict__ Pl)
{
    const size_t row = blockIdx.x;
    const float* s   = S    + row * SEQ;
    const int*   m   = mask + row * SEQ;
    const int    tid = threadIdx.x;
    const float  scale = 0.03125f;

    float v[8];
    #pragma unroll
    for (int u = 0; u < 2; u++) {
        const int b = u * 1024 + tid * 4;
        const float4 sv = *(const float4*)(s + b);
        const int4   mv = *(const int4*)(m + b);
        v[u*4+0] = mv.x ? sv.x * scale : -1e30f;
        v[u*4+1] = mv.y ? sv.y * scale : -1e30f;
        v[u*4+2] = mv.z ? sv.z * scale : -1e30f;
        v[u*4+3] = mv.w ? sv.w * scale : -1e30f;
    }

    __shared__ float red[8];
    float mx = v[0];
    #pragma unroll
    for (int i = 1; i < 8; i++) mx = fmaxf(mx, v[i]);
    #pragma unroll
    for (int o = 16; o > 0; o >>= 1) mx = fmaxf(mx, __shfl_xor_sync(0xffffffffu, mx, o));
    if ((tid & 31) == 0) red[tid >> 5] = mx;
    __syncthreads();
    mx = red[0];
    #pragma unroll
    for (int w = 1; w < 8; w++) mx = fmaxf(mx, red[w]);
    __syncthreads();

    float sum = 0.f;
    #pragma unroll
    for (int i = 0; i < 8; i++) { v[i] = expf(v[i] - mx); sum += v[i]; }
    #pragma unroll
    for (int o = 16; o > 0; o >>= 1) sum += __shfl_xor_sync(0xffffffffu, sum, o);
    if ((tid & 31) == 0) red[tid >> 5] = sum;
    __syncthreads();
    sum = red[0];
    #pragma unroll
    for (int w = 1; w < 8; w++) sum += red[w];

    const float inv = 1.0f / sum;
    #pragma unroll
    for (int u = 0; u < 2; u++) {
        const int b = u * 1024 + tid * 4;
        #pragma unroll
        for (int p = 0; p < 4; p += 2) {
            const float p0 = v[u*4+p] * inv, p1 = v[u*4+p+1] * inv;
            const __nv_bfloat16 h0 = __float2bfloat16(p0);
            const __nv_bfloat16 h1 = __float2bfloat16(p1);
            __nv_bfloat162 hh; hh.x = h0; hh.y = h1;
            __nv_bfloat162 ll;
            ll.x = __float2bfloat16(p0 - __bfloat162float(h0));
            ll.y = __float2bfloat16(p1 - __bfloat162float(h1));
            *(__nv_bfloat162*)(Ph + row * SEQ + b + p) = hh;
            *(__nv_bfloat162*)(Pl + row * SEQ + b + p) = ll;
        }
    }
}

// ---------------------------------------------------------------------------
extern "C" void kernel_launch(void* const* d_in, const int* in_sizes, int n_in,
                              void* d_out, int out_size)
{
    const float* x    = (const float*)d_in[0];
    const int*   mask = (const int*)  d_in[1];
    const float* Wqk  = (const float*)d_in[2];
    const float* Wvc  = (const float*)d_in[3];
    float*       out  = (float*)d_out;

    __nv_bfloat16 *xh, *xl, *xth, *xtl, *wqh, *wql, *wvh, *wvl, *qh, *ql, *ph, *pl, *ah, *al;
    float* s;
    cudaGetSymbolAddress((void**)&xh,  g_xh);  cudaGetSymbolAddress((void**)&xl,  g_xl);
    cudaGetSymbolAddress((void**)&xth, g_xth); cudaGetSymbolAddress((void**)&xtl, g_xtl);
    cudaGetSymbolAddress((void**)&wqh, g_wqh); cudaGetSymbolAddress((void**)&wql, g_wql);
    cudaGetSymbolAddress((void**)&wvh, g_wvh); cudaGetSymbolAddress((void**)&wvl, g_wvl);
    cudaGetSymbolAddress((void**)&qh,  g_qh);  cudaGetSymbolAddress((void**)&ql,  g_ql);
    cudaGetSymbolAddress((void**)&s,   g_s);
    cudaGetSymbolAddress((void**)&ph,  g_ph);  cudaGetSymbolAddress((void**)&pl,  g_pl);
    cudaGetSymbolAddress((void**)&ah,  g_ah);  cudaGetSymbolAddress((void**)&al,  g_al);

    cudaFuncSetAttribute(mma_gemm_nt<0>, cudaFuncAttributeMaxDynamicSharedMemorySize, GEMM_SMEM);
    cudaFuncSetAttribute(mma_gemm_nt<1>, cudaFuncAttributeMaxDynamicSharedMemorySize, GEMM_SMEM);

    const long long sXD = (long long)SEQ * DIM;
    const long long sSS = (long long)SEQ * SEQ;
    const long long sTX = (long long)DIM * SEQ;

    // --- input preprocessing ---
    {
        const int nx4 = NB * SEQ * DIM / 4;
        split_kernel<<<nx4 / 256, 256>>>(x, xh, xl, nx4);
        const int nw4 = DIM * DIM / 4;
        split_kernel<<<nw4 / 256, 256>>>(Wqk, wqh, wql, nw4);
        split_kernel<<<nw4 / 256, 256>>>(Wvc, wvh, wvl, nw4);
        transpose_split_kernel<<<dim3(DIM / 32, SEQ / 32, NB), 256>>>(x, xth, xtl);
    }

    // 1) q = x · Wqk^T -> split
    mma_gemm_nt<1><<<dim3(DIM / 128, (NB * SEQ) / 128, 1), 256, GEMM_SMEM>>>(
        xh, xl, wqh, wql, nullptr, qh, ql, DIM, DIM, 0, 0, 0);

    // 2) S_b = q_b · x_b^T -> fp32
    mma_gemm_nt<0><<<dim3(SEQ / 128, SEQ / 128, NB), 256, GEMM_SMEM>>>(
        qh, ql, xh, xl, s, nullptr, nullptr, DIM, SEQ, sXD, sXD, sSS);

    // 3) P = softmax(mask ? S/32 : -inf) -> split
    softmax_mask_split<<<NB * SEQ, 256>>>(s, mask, ph, pl);

    // 4) att_b = P_b · (xT_b)^T -> split
    mma_gemm_nt<1><<<dim3(DIM / 128, SEQ / 128, NB), 256, GEMM_SMEM>>>(
        ph, pl, xth, xtl, nullptr, ah, al, SEQ, DIM, sSS, sTX, sXD);

    // 5) out = att · Wvc^T -> fp32
    mma_gemm_nt<0><<<dim3(DIM / 128, (NB * SEQ) / 128, 1), 256, GEMM_SMEM>>>(
        ah, al, wvh, wvl, out, nullptr, nullptr, DIM, DIM, 0, 0, 0);
}

// round 4
// speedup vs baseline: 3.7554x; 1.4770x over previous
#include <cuda_runtime.h>
#include <cuda_fp16.h>
#include <math.h>
#include <stdint.h>

// Problem constants: N=4, n=2048, d=1024
#define NB   4
#define SEQ  2048
#define DIM  1024

// ---------------------------------------------------------------------------
// Scratch (__device__ globals; allocation-free rule)
// ---------------------------------------------------------------------------
__device__ __half g_xh [(size_t)NB*SEQ*DIM];
__device__ __half g_xl [(size_t)NB*SEQ*DIM];
__device__ __half g_xth[(size_t)NB*DIM*SEQ];   // x^T per batch [DIM,SEQ], hi only
__device__ __half g_wqh[(size_t)DIM*DIM];      // hi only
__device__ __half g_wvh[(size_t)DIM*DIM];      // hi only
__device__ __half g_qh [(size_t)NB*SEQ*DIM];
__device__ __half g_ql [(size_t)NB*SEQ*DIM];
__device__ float  g_s  [(size_t)NB*SEQ*SEQ];
__device__ __half g_ph [(size_t)NB*SEQ*SEQ];   // 1024 * p (power-of-2 scaled)
__device__ __half g_pl [(size_t)NB*SEQ*SEQ];
__device__ __half g_ah [(size_t)NB*SEQ*DIM];   // 1024 * att
__device__ __half g_al [(size_t)NB*SEQ*DIM];

// ---------------------------------------------------------------------------
// Baseline-PTX helpers (compute_100-safe: ldmatrix / mma.sync / cp.async)
// ---------------------------------------------------------------------------
__device__ __forceinline__ uint32_t smem_u32(const void* p) {
    uint32_t a;
    asm("{ .reg .u64 t; cvta.to.shared.u64 t, %1; cvt.u32.u64 %0, t; }" : "=r"(a) : "l"(p));
    return a;
}
__device__ __forceinline__ void ldsm4(uint32_t* r, uint32_t a) {
    asm volatile("ldmatrix.sync.aligned.m8n8.x4.shared.b16 {%0,%1,%2,%3}, [%4];"
        : "=r"(r[0]), "=r"(r[1]), "=r"(r[2]), "=r"(r[3]) : "r"(a));
}
__device__ __forceinline__ void mma16816(float* c, const uint32_t* a, const uint32_t* b) {
    asm volatile("mma.sync.aligned.m16n8k16.row.col.f32.f16.f16.f32 "
        "{%0,%1,%2,%3}, {%4,%5,%6,%7}, {%8,%9}, {%0,%1,%2,%3};"
        : "+f"(c[0]), "+f"(c[1]), "+f"(c[2]), "+f"(c[3])
        : "r"(a[0]), "r"(a[1]), "r"(a[2]), "r"(a[3]), "r"(b[0]), "r"(b[1]));
}
#define CP_ASYNC16(so, gp) \
    asm volatile("cp.async.cg.shared.global [%0], [%1], 16;" :: "r"(so), "l"(gp) : "memory")
#define CP_COMMIT() asm volatile("cp.async.commit_group;" ::: "memory")
#define CP_WAIT2()  asm volatile("cp.async.wait_group 2;" ::: "memory")

// SW64-style swizzle for 64B rows
#define SWZ64(o) ((o) ^ (((o) >> 3) & 0x30))

// ---------------------------------------------------------------------------
// 2-product split-fp16 NT GEMM:
//   C[M,N] = (Ah + Al)[M,K] · Bh[N,K]^T  (fp32 accum)  ≈ A · B
// MODE 0: write fp32 C * escale. MODE 1: write fp16 split of C * escale.
// 128x128 CTA tile, BK=32, 4-stage cp.async pipeline, 8 warps (4m x 2n).
// ---------------------------------------------------------------------------
#define TILE_B  8192            // 128 rows x 64 bytes
#define STAGE_B 24576           // Ah, Al, Bh tiles
#define NSTAGE  4
#define GEMM_SMEM (NSTAGE * STAGE_B)

template <int MODE>
__global__ __launch_bounds__(256, 1)
void mma_gemm_nt(const __half* __restrict__ Ah, const __half* __restrict__ Al,
                 const __half* __restrict__ Bh,
                 float* __restrict__ Cf, __half* __restrict__ Ch, __half* __restrict__ Cl,
                 int K, int ldc, long long sA, long long sB, long long sC, float escale)
{
    extern __shared__ char smraw[];
    const uint32_t base = smem_u32(smraw);

    const int tid  = threadIdx.x;
    const int wid  = tid >> 5;
    const int lid  = tid & 31;
    const int bz   = blockIdx.z;
    const int row0 = blockIdx.y * 128;
    const int col0 = blockIdx.x * 128;

    const int warp_m = wid >> 1;          // 0..3 -> 32-row slab
    const int warp_n = wid & 1;           // 0..1 -> 64-col slab

    const __half* src[3] = { Ah + (size_t)bz * sA, Al + (size_t)bz * sA,
                             Bh + (size_t)bz * sB };
    const int rb[3] = { row0, row0, col0 };

    const int nCh = K >> 5;               // chunks of 32

    // loader: 1536 x 16B copies; id -> tile(3) x row(128) x c16(4)
    auto issue_stage = [&](int i) {
        const uint32_t stage = base + (uint32_t)(i & 3) * STAGE_B;
        const int k0 = i << 5;
        #pragma unroll
        for (int g = 0; g < 6; g++) {
            const int id   = tid + g * 256;
            const int tile = id >> 9;
            const int rem  = id & 511;
            const int r    = rem >> 2;
            const int c16  = rem & 3;
            const __half* gp = src[tile] + (size_t)(rb[tile] + r) * K + k0 + c16 * 8;
            const uint32_t so = stage + (uint32_t)tile * TILE_B + SWZ64(r * 64 + c16 * 16);
            CP_ASYNC16(so, gp);
        }
    };

    float acc[2][8][4];
    #pragma unroll
    for (int mt = 0; mt < 2; mt++)
        #pragma unroll
        for (int nt = 0; nt < 8; nt++)
            #pragma unroll
            for (int e = 0; e < 4; e++) acc[mt][nt][e] = 0.f;

    issue_stage(0); CP_COMMIT();
    issue_stage(1); CP_COMMIT();
    issue_stage(2); CP_COMMIT();

    // ldmatrix lane addressing
    const int a_r_lane = ((lid >> 3) & 1) * 8 + (lid & 7);
    const int a_c_lane = lid >> 4;
    const int b_r_lane = (lid >> 4) * 8 + (lid & 7);
    const int b_c_lane = (lid >> 3) & 1;

    for (int i = 0; i < nCh; i++) {
        CP_WAIT2();
        __syncthreads();                 // stage i visible; stage (i-1) reads done
        if (i + 3 < nCh) issue_stage(i + 3);
        CP_COMMIT();

        const uint32_t stage = base + (uint32_t)(i & 3) * STAGE_B;
        const uint32_t sAh = stage;
        const uint32_t sAl = stage + TILE_B;
        const uint32_t sBh = stage + 2 * TILE_B;

        #pragma unroll
        for (int s = 0; s < 2; s++) {    // two k16 steps per 32-chunk
            uint32_t afh[2][4], afl[2][4], bfh[4][4];
            #pragma unroll
            for (int mt = 0; mt < 2; mt++) {
                const int row = warp_m * 32 + mt * 16 + a_r_lane;
                const int off = SWZ64(row * 64 + (2 * s + a_c_lane) * 16);
                ldsm4(afh[mt], sAh + off);
                ldsm4(afl[mt], sAl + off);
            }
            #pragma unroll
            for (int nt = 0; nt < 4; nt++) {
                const int row = warp_n * 64 + nt * 16 + b_r_lane;
                const int off = SWZ64(row * 64 + (2 * s + b_c_lane) * 16);
                ldsm4(bfh[nt], sBh + off);
            }
            #pragma unroll
            for (int mt = 0; mt < 2; mt++)
                #pragma unroll
                for (int nt = 0; nt < 8; nt++)
                    mma16816(acc[mt][nt], afh[mt], &bfh[nt >> 1][(nt & 1) * 2]);
            #pragma unroll
            for (int mt = 0; mt < 2; mt++)
                #pragma unroll
                for (int nt = 0; nt < 8; nt++)
                    mma16816(acc[mt][nt], afl[mt], &bfh[nt >> 1][(nt & 1) * 2]);
        }
    }

    // Epilogue
    const int er = lid >> 2;
    const int ec = (lid & 3) * 2;
    #pragma unroll
    for (int mt = 0; mt < 2; mt++) {
        #pragma unroll
        for (int nt = 0; nt < 8; nt++) {
            const int r_g = row0 + warp_m * 32 + mt * 16 + er;
            const int c_g = col0 + warp_n * 64 + nt * 8 + ec;
            const size_t o0 = (size_t)bz * sC + (size_t)r_g * ldc + c_g;
            const size_t o1 = o0 + (size_t)8 * ldc;
            if (MODE == 0) {
                Cf[o0]     = acc[mt][nt][0] * escale;
                Cf[o0 + 1] = acc[mt][nt][1] * escale;
                Cf[o1]     = acc[mt][nt][2] * escale;
                Cf[o1 + 1] = acc[mt][nt][3] * escale;
            } else {
                #pragma unroll
                for (int h = 0; h < 2; h++) {
                    const float v0 = acc[mt][nt][h * 2]     * escale;
                    const float v1 = acc[mt][nt][h * 2 + 1] * escale;
                    const __half h0 = __float2half(v0);
                    const __half h1 = __float2half(v1);
                    __half2 hh; hh.x = h0; hh.y = h1;
                    __half2 ll;
                    ll.x = __float2half(v0 - __half2float(h0));
                    ll.y = __float2half(v1 - __half2float(h1));
                    const size_t o = h ? o1 : o0;
                    *(__half2*)(Ch + o) = hh;
                    *(__half2*)(Cl + o) = ll;
                }
            }
        }
    }
}

// ---------------------------------------------------------------------------
// fp32 -> (fp16 hi, fp16 lo) elementwise split
// ---------------------------------------------------------------------------
__global__ __launch_bounds__(256)
void split_kernel(const float* __restrict__ s, __half* __restrict__ h,
                  __half* __restrict__ l, int n4)
{
    const int i = blockIdx.x * blockDim.x + threadIdx.x;
    if (i >= n4) return;
    const float4 v = ((const float4*)s)[i];
    const __half h0 = __float2half(v.x), h1 = __float2half(v.y);
    const __half h2 = __float2half(v.z), h3 = __float2half(v.w);
    __half2 a, b, c, d;
    a.x = h0; a.y = h1; b.x = h2; b.y = h3;
    c.x = __float2half(v.x - __half2float(h0));
    c.y = __float2half(v.y - __half2float(h1));
    d.x = __float2half(v.z - __half2float(h2));
    d.y = __float2half(v.w - __half2float(h3));
    *(__half2*)(h + (size_t)i * 4)     = a;
    *(__half2*)(h + (size_t)i * 4 + 2) = b;
    *(__half2*)(l + (size_t)i * 4)     = c;
    *(__half2*)(l + (size_t)i * 4 + 2) = d;
}

// fp32 -> fp16 (hi only), for weights
__global__ __launch_bounds__(256)
void convert_kernel(const float* __restrict__ s, __half* __restrict__ h, int n4)
{
    const int i = blockIdx.x * blockDim.x + threadIdx.x;
    if (i >= n4) return;
    const float4 v = ((const float4*)s)[i];
    __half2 a, b;
    a.x = __float2half(v.x); a.y = __float2half(v.y);
    b.x = __float2half(v.z); b.y = __float2half(v.w);
    *(__half2*)(h + (size_t)i * 4)     = a;
    *(__half2*)(h + (size_t)i * 4 + 2) = b;
}

// ---------------------------------------------------------------------------
// x [NB,SEQ,DIM] -> xT [NB,DIM,SEQ] fp16 (hi only)
// ---------------------------------------------------------------------------
__global__ __launch_bounds__(256)
void transpose_h_kernel(const float* __restrict__ x, __half* __restrict__ th)
{
    __shared__ float t[32][33];
    const int b  = blockIdx.z;
    const int d0 = blockIdx.x * 32;
    const int k0 = blockIdx.y * 32;
    const int tx = threadIdx.x & 31;
    const int ty = threadIdx.x >> 5;
    #pragma unroll
    for (int j = 0; j < 32; j += 8)
        t[ty + j][tx] = x[(size_t)b * SEQ * DIM + (size_t)(k0 + ty + j) * DIM + d0 + tx];
    __syncthreads();
    #pragma unroll
    for (int j = 0; j < 32; j += 8) {
        const size_t off = (size_t)b * DIM * SEQ + (size_t)(d0 + ty + j) * SEQ + k0 + tx;
        th[off] = __float2half(t[tx][ty + j]);
    }
}

// ---------------------------------------------------------------------------
// scale + mask + softmax; outputs split fp16 of (1024 * p)
// ---------------------------------------------------------------------------
__global__ __launch_bounds__(256)
void softmax_mask_split(const float* __restrict__ S, const int* __restrict__ mask,
                        __half* __restrict__ Ph, __half* __restrict__ Pl)
{
    const size_t row = blockIdx.x;
    const float* s   = S    + row * SEQ;
    const int*   m   = mask + row * SEQ;
    const int    tid = threadIdx.x;
    const float  scale = 0.03125f;   // 1/sqrt(1024)

    float v[8];
    #pragma unroll
    for (int u = 0; u < 2; u++) {
        const int b = u * 1024 + tid * 4;
        const float4 sv = *(const float4*)(s + b);
        const int4   mv = *(const int4*)(m + b);
        v[u*4+0] = mv.x ? sv.x * scale : -1e30f;
        v[u*4+1] = mv.y ? sv.y * scale : -1e30f;
        v[u*4+2] = mv.z ? sv.z * scale : -1e30f;
        v[u*4+3] = mv.w ? sv.w * scale : -1e30f;
    }

    __shared__ float red[8];
    float mx = v[0];
    #pragma unroll
    for (int i = 1; i < 8; i++) mx = fmaxf(mx, v[i]);
    #pragma unroll
    for (int o = 16; o > 0; o >>= 1) mx = fmaxf(mx, __shfl_xor_sync(0xffffffffu, mx, o));
    if ((tid & 31) == 0) red[tid >> 5] = mx;
    __syncthreads();
    mx = red[0];
    #pragma unroll
    for (int w = 1; w < 8; w++) mx = fmaxf(mx, red[w]);
    __syncthreads();

    float sum = 0.f;
    #pragma unroll
    for (int i = 0; i < 8; i++) { v[i] = expf(v[i] - mx); sum += v[i]; }
    #pragma unroll
    for (int o = 16; o > 0; o >>= 1) sum += __shfl_xor_sync(0xffffffffu, sum, o);
    if ((tid & 31) == 0) red[tid >> 5] = sum;
    __syncthreads();
    sum = red[0];
    #pragma unroll
    for (int w = 1; w < 8; w++) sum += red[w];

    const float inv = 1024.0f / sum;     // scale probs by 1024 (exact pow2)
    #pragma unroll
    for (int u = 0; u < 2; u++) {
        const int b = u * 1024 + tid * 4;
        #pragma unroll
        for (int p = 0; p < 4; p += 2) {
            const float p0 = v[u*4+p] * inv, p1 = v[u*4+p+1] * inv;
            const __half h0 = __float2half(p0);
            const __half h1 = __float2half(p1);
            __half2 hh; hh.x = h0; hh.y = h1;
            __half2 ll;
            ll.x = __float2half(p0 - __half2float(h0));
            ll.y = __float2half(p1 - __half2float(h1));
            *(__half2*)(Ph + row * SEQ + b + p) = hh;
            *(__half2*)(Pl + row * SEQ + b + p) = ll;
        }
    }
}

// ---------------------------------------------------------------------------
extern "C" void kernel_launch(void* const* d_in, const int* in_sizes, int n_in,
                              void* d_out, int out_size)
{
    const float* x    = (const float*)d_in[0];
    const int*   mask = (const int*)  d_in[1];
    const float* Wqk  = (const float*)d_in[2];
    const float* Wvc  = (const float*)d_in[3];
    float*       out  = (float*)d_out;

    __half *xh, *xl, *xth, *wqh, *wvh, *qh, *ql, *ph, *pl, *ah, *al;
    float* s;
    cudaGetSymbolAddress((void**)&xh,  g_xh);  cudaGetSymbolAddress((void**)&xl,  g_xl);
    cudaGetSymbolAddress((void**)&xth, g_xth);
    cudaGetSymbolAddress((void**)&wqh, g_wqh); cudaGetSymbolAddress((void**)&wvh, g_wvh);
    cudaGetSymbolAddress((void**)&qh,  g_qh);  cudaGetSymbolAddress((void**)&ql,  g_ql);
    cudaGetSymbolAddress((void**)&s,   g_s);
    cudaGetSymbolAddress((void**)&ph,  g_ph);  cudaGetSymbolAddress((void**)&pl,  g_pl);
    cudaGetSymbolAddress((void**)&ah,  g_ah);  cudaGetSymbolAddress((void**)&al,  g_al);

    cudaFuncSetAttribute(mma_gemm_nt<0>, cudaFuncAttributeMaxDynamicSharedMemorySize, GEMM_SMEM);
    cudaFuncSetAttribute(mma_gemm_nt<1>, cudaFuncAttributeMaxDynamicSharedMemorySize, GEMM_SMEM);

    const long long sXD = (long long)SEQ * DIM;
    const long long sSS = (long long)SEQ * SEQ;
    const long long sTX = (long long)DIM * SEQ;

    // --- input preprocessing ---
    {
        const int nx4 = NB * SEQ * DIM / 4;
        split_kernel<<<nx4 / 256, 256>>>(x, xh, xl, nx4);
        const int nw4 = DIM * DIM / 4;
        convert_kernel<<<nw4 / 256, 256>>>(Wqk, wqh, nw4);
        convert_kernel<<<nw4 / 256, 256>>>(Wvc, wvh, nw4);
        transpose_h_kernel<<<dim3(DIM / 32, SEQ / 32, NB), 256>>>(x, xth);
    }

    // 1) q = (xh+xl) · wqh^T -> split fp16
    mma_gemm_nt<1><<<dim3(DIM / 128, (NB * SEQ) / 128, 1), 256, GEMM_SMEM>>>(
        xh, xl, wqh, nullptr, qh, ql, DIM, DIM, 0, 0, 0, 1.0f);

    // 2) S_b = (qh+ql)_b · xh_b^T -> fp32
    mma_gemm_nt<0><<<dim3(SEQ / 128, SEQ / 128, NB), 256, GEMM_SMEM>>>(
        qh, ql, xh, s, nullptr, nullptr, DIM, SEQ, sXD, sXD, sSS, 1.0f);

    // 3) P = softmax(mask ? S/32 : -inf); write split of 1024*P
    softmax_mask_split<<<NB * SEQ, 256>>>(s, mask, ph, pl);

    // 4) 1024*att_b = (ph+pl)_b · xth_b^T -> split fp16 (keep 1024 factor)
    mma_gemm_nt<1><<<dim3(DIM / 128, SEQ / 128, NB), 256, GEMM_SMEM>>>(
        ph, pl, xth, nullptr, ah, al, SEQ, DIM, sSS, sTX, sXD, 1.0f);

    // 5) out = (1024*att · wvh^T) / 1024 -> fp32
    mma_gemm_nt<0><<<dim3(DIM / 128, (NB * SEQ) / 128, 1), 256, GEMM_SMEM>>>(
        ah, al, wvh, out, nullptr, nullptr, DIM, DIM, 0, 0, 0, 1.0f / 1024.0f);
}

// round 5
// speedup vs baseline: 7.2415x; 1.9283x over previous
#include <cuda_runtime.h>
#include <cuda_fp16.h>
#include <math.h>
#include <stdint.h>

// Problem constants: N=4, n=2048, d=1024
#define NB   4
#define SEQ  2048
#define DIM  1024

// ---------------------------------------------------------------------------
// Scratch (__device__ globals; allocation-free rule)
// ---------------------------------------------------------------------------
__device__ __half g_xh [(size_t)NB*SEQ*DIM];
__device__ __half g_xth[(size_t)NB*DIM*SEQ];   // x^T per batch [DIM,SEQ]
__device__ __half g_wqh[(size_t)DIM*DIM];
__device__ __half g_wvh[(size_t)DIM*DIM];
__device__ __half g_qh [(size_t)NB*SEQ*DIM];
__device__ float  g_s  [(size_t)NB*SEQ*SEQ];
__device__ __half g_ph [(size_t)NB*SEQ*SEQ];   // 1024 * p (power-of-2 scaled)
__device__ __half g_ah [(size_t)NB*SEQ*DIM];   // 1024 * att

// ---------------------------------------------------------------------------
// Baseline-PTX helpers (compute_100-safe)
// ---------------------------------------------------------------------------
__device__ __forceinline__ uint32_t smem_u32(const void* p) {
    uint32_t a;
    asm("{ .reg .u64 t; cvta.to.shared.u64 t, %1; cvt.u32.u64 %0, t; }" : "=r"(a) : "l"(p));
    return a;
}
__device__ __forceinline__ void ldsm4(uint32_t* r, uint32_t a) {
    asm volatile("ldmatrix.sync.aligned.m8n8.x4.shared.b16 {%0,%1,%2,%3}, [%4];"
        : "=r"(r[0]), "=r"(r[1]), "=r"(r[2]), "=r"(r[3]) : "r"(a));
}
__device__ __forceinline__ void mma16816(float* c, const uint32_t* a, const uint32_t* b) {
    asm volatile("mma.sync.aligned.m16n8k16.row.col.f32.f16.f16.f32 "
        "{%0,%1,%2,%3}, {%4,%5,%6,%7}, {%8,%9}, {%0,%1,%2,%3};"
        : "+f"(c[0]), "+f"(c[1]), "+f"(c[2]), "+f"(c[3])
        : "r"(a[0]), "r"(a[1]), "r"(a[2]), "r"(a[3]), "r"(b[0]), "r"(b[1]));
}
#define CP_ASYNC16(so, gp) \
    asm volatile("cp.async.cg.shared.global [%0], [%1], 16;" :: "r"(so), "l"(gp) : "memory")
#define CP_COMMIT() asm volatile("cp.async.commit_group;" ::: "memory")
#define CP_WAIT2()  asm volatile("cp.async.wait_group 2;" ::: "memory")

// SW64-style swizzle for 64B rows
#define SWZ64(o) ((o) ^ (((o) >> 3) & 0x30))

// ---------------------------------------------------------------------------
// Single-product fp16 NT GEMM: C[M,N] = A[M,K] · B[N,K]^T (fp32 accum)
// MODE 0: write fp32 C * escale. MODE 1: write fp16 C * escale.
// 128x128 CTA tile, BK=32, 4-stage cp.async pipeline, 8 warps (4m x 2n),
// 2 CTAs/SM.
// ---------------------------------------------------------------------------
#define TILE_B  8192            // 128 rows x 64 bytes
#define STAGE_B 16384           // A, B tiles
#define NSTAGE  4
#define GEMM_SMEM (NSTAGE * STAGE_B)

template <int MODE>
__global__ __launch_bounds__(256, 2)
void mma_gemm_nt(const __half* __restrict__ Ah, const __half* __restrict__ Bh,
                 float* __restrict__ Cf, __half* __restrict__ Ch,
                 int K, int ldc, long long sA, long long sB, long long sC, float escale)
{
    extern __shared__ char smraw[];
    const uint32_t base = smem_u32(smraw);

    const int tid  = threadIdx.x;
    const int wid  = tid >> 5;
    const int lid  = tid & 31;
    const int bz   = blockIdx.z;
    const int row0 = blockIdx.y * 128;
    const int col0 = blockIdx.x * 128;

    const int warp_m = wid >> 1;          // 0..3 -> 32-row slab
    const int warp_n = wid & 1;           // 0..1 -> 64-col slab

    const __half* src[2] = { Ah + (size_t)bz * sA, Bh + (size_t)bz * sB };
    const int rb[2] = { row0, col0 };

    const int nCh = K >> 5;               // chunks of 32

    // loader: 1024 x 16B copies; id -> tile(2) x row(128) x c16(4)
    auto issue_stage = [&](int i) {
        const uint32_t stage = base + (uint32_t)(i & 3) * STAGE_B;
        const int k0 = i << 5;
        #pragma unroll
        for (int g = 0; g < 4; g++) {
            const int id   = tid + g * 256;
            const int tile = id >> 9;
            const int rem  = id & 511;
            const int r    = rem >> 2;
            const int c16  = rem & 3;
            const __half* gp = src[tile] + (size_t)(rb[tile] + r) * K + k0 + c16 * 8;
            const uint32_t so = stage + (uint32_t)tile * TILE_B + SWZ64(r * 64 + c16 * 16);
            CP_ASYNC16(so, gp);
        }
    };

    float acc[2][8][4];
    #pragma unroll
    for (int mt = 0; mt < 2; mt++)
        #pragma unroll
        for (int nt = 0; nt < 8; nt++)
            #pragma unroll
            for (int e = 0; e < 4; e++) acc[mt][nt][e] = 0.f;

    issue_stage(0); CP_COMMIT();
    issue_stage(1); CP_COMMIT();
    issue_stage(2); CP_COMMIT();

    // ldmatrix lane addressing
    const int a_r_lane = ((lid >> 3) & 1) * 8 + (lid & 7);
    const int a_c_lane = lid >> 4;
    const int b_r_lane = (lid >> 4) * 8 + (lid & 7);
    const int b_c_lane = (lid >> 3) & 1;

    for (int i = 0; i < nCh; i++) {
        CP_WAIT2();
        __syncthreads();                 // stage i visible; stage (i-1) reads done
        if (i + 3 < nCh) issue_stage(i + 3);
        CP_COMMIT();

        const uint32_t stage = base + (uint32_t)(i & 3) * STAGE_B;
        const uint32_t sA = stage;
        const uint32_t sB = stage + TILE_B;

        #pragma unroll
        for (int s = 0; s < 2; s++) {    // two k16 steps per 32-chunk
            uint32_t af[2][4], bf[4][4];
            #pragma unroll
            for (int mt = 0; mt < 2; mt++) {
                const int row = warp_m * 32 + mt * 16 + a_r_lane;
                const int off = SWZ64(row * 64 + (2 * s + a_c_lane) * 16);
                ldsm4(af[mt], sA + off);
            }
            #pragma unroll
            for (int nt = 0; nt < 4; nt++) {
                const int row = warp_n * 64 + nt * 16 + b_r_lane;
                const int off = SWZ64(row * 64 + (2 * s + b_c_lane) * 16);
                ldsm4(bf[nt], sB + off);
            }
            #pragma unroll
            for (int mt = 0; mt < 2; mt++)
                #pragma unroll
                for (int nt = 0; nt < 8; nt++)
                    mma16816(acc[mt][nt], af[mt], &bf[nt >> 1][(nt & 1) * 2]);
        }
    }

    // Epilogue
    const int er = lid >> 2;
    const int ec = (lid & 3) * 2;
    #pragma unroll
    for (int mt = 0; mt < 2; mt++) {
        #pragma unroll
        for (int nt = 0; nt < 8; nt++) {
            const int r_g = row0 + warp_m * 32 + mt * 16 + er;
            const int c_g = col0 + warp_n * 64 + nt * 8 + ec;
            const size_t o0 = (size_t)bz * sC + (size_t)r_g * ldc + c_g;
            const size_t o1 = o0 + (size_t)8 * ldc;
            if (MODE == 0) {
                Cf[o0]     = acc[mt][nt][0] * escale;
                Cf[o0 + 1] = acc[mt][nt][1] * escale;
                Cf[o1]     = acc[mt][nt][2] * escale;
                Cf[o1 + 1] = acc[mt][nt][3] * escale;
            } else {
                __half2 h0, h1;
                h0.x = __float2half(acc[mt][nt][0] * escale);
                h0.y = __float2half(acc[mt][nt][1] * escale);
                h1.x = __float2half(acc[mt][nt][2] * escale);
                h1.y = __float2half(acc[mt][nt][3] * escale);
                *(__half2*)(Ch + o0) = h0;
                *(__half2*)(Ch + o1) = h1;
            }
        }
    }
}

// ---------------------------------------------------------------------------
// fp32 -> fp16 convert
// ---------------------------------------------------------------------------
__global__ __launch_bounds__(256)
void convert_kernel(const float* __restrict__ s, __half* __restrict__ h, int n4)
{
    const int i = blockIdx.x * blockDim.x + threadIdx.x;
    if (i >= n4) return;
    const float4 v = ((const float4*)s)[i];
    __half2 a, b;
    a.x = __float2half(v.x); a.y = __float2half(v.y);
    b.x = __float2half(v.z); b.y = __float2half(v.w);
    *(__half2*)(h + (size_t)i * 4)     = a;
    *(__half2*)(h + (size_t)i * 4 + 2) = b;
}

// ---------------------------------------------------------------------------
// x [NB,SEQ,DIM] -> xT [NB,DIM,SEQ] fp16
// ---------------------------------------------------------------------------
__global__ __launch_bounds__(256)
void transpose_h_kernel(const float* __restrict__ x, __half* __restrict__ th)
{
    __shared__ float t[32][33];
    const int b  = blockIdx.z;
    const int d0 = blockIdx.x * 32;
    const int k0 = blockIdx.y * 32;
    const int tx = threadIdx.x & 31;
    const int ty = threadIdx.x >> 5;
    #pragma unroll
    for (int j = 0; j < 32; j += 8)
        t[ty + j][tx] = x[(size_t)b * SEQ * DIM + (size_t)(k0 + ty + j) * DIM + d0 + tx];
    __syncthreads();
    #pragma unroll
    for (int j = 0; j < 32; j += 8) {
        const size_t off = (size_t)b * DIM * SEQ + (size_t)(d0 + ty + j) * SEQ + k0 + tx;
        th[off] = __float2half(t[tx][ty + j]);
    }
}

// ---------------------------------------------------------------------------
// scale + mask + softmax; outputs fp16 of (1024 * p)
// ---------------------------------------------------------------------------
__global__ __launch_bounds__(256)
void softmax_mask_h(const float* __restrict__ S, const int* __restrict__ mask,
                    __half* __restrict__ Ph)
{
    const size_t row = blockIdx.x;
    const float* s   = S    + row * SEQ;
    const int*   m   = mask + row * SEQ;
    const int    tid = threadIdx.x;
    const float  scale = 0.03125f;   // 1/sqrt(1024)

    float v[8];
    #pragma unroll
    for (int u = 0; u < 2; u++) {
        const int b = u * 1024 + tid * 4;
        const float4 sv = *(const float4*)(s + b);
        const int4   mv = *(const int4*)(m + b);
        v[u*4+0] = mv.x ? sv.x * scale : -1e30f;
        v[u*4+1] = mv.y ? sv.y * scale : -1e30f;
        v[u*4+2] = mv.z ? sv.z * scale : -1e30f;
        v[u*4+3] = mv.w ? sv.w * scale : -1e30f;
    }

    __shared__ float red[8];
    float mx = v[0];
    #pragma unroll
    for (int i = 1; i < 8; i++) mx = fmaxf(mx, v[i]);
    #pragma unroll
    for (int o = 16; o > 0; o >>= 1) mx = fmaxf(mx, __shfl_xor_sync(0xffffffffu, mx, o));
    if ((tid & 31) == 0) red[tid >> 5] = mx;
    __syncthreads();
    mx = red[0];
    #pragma unroll
    for (int w = 1; w < 8; w++) mx = fmaxf(mx, red[w]);
    __syncthreads();

    float sum = 0.f;
    #pragma unroll
    for (int i = 0; i < 8; i++) { v[i] = expf(v[i] - mx); sum += v[i]; }
    #pragma unroll
    for (int o = 16; o > 0; o >>= 1) sum += __shfl_xor_sync(0xffffffffu, sum, o);
    if ((tid & 31) == 0) red[tid >> 5] = sum;
    __syncthreads();
    sum = red[0];
    #pragma unroll
    for (int w = 1; w < 8; w++) sum += red[w];

    const float inv = 1024.0f / sum;     // scale probs by 1024 (exact pow2)
    #pragma unroll
    for (int u = 0; u < 2; u++) {
        const int b = u * 1024 + tid * 4;
        __half2 p0, p1;
        p0.x = __float2half(v[u*4+0] * inv);
        p0.y = __float2half(v[u*4+1] * inv);
        p1.x = __float2half(v[u*4+2] * inv);
        p1.y = __float2half(v[u*4+3] * inv);
        *(__half2*)(Ph + row * SEQ + b)     = p0;
        *(__half2*)(Ph + row * SEQ + b + 2) = p1;
    }
}

// ---------------------------------------------------------------------------
extern "C" void kernel_launch(void* const* d_in, const int* in_sizes, int n_in,
                              void* d_out, int out_size)
{
    const float* x    = (const float*)d_in[0];
    const int*   mask = (const int*)  d_in[1];
    const float* Wqk  = (const float*)d_in[2];
    const float* Wvc  = (const float*)d_in[3];
    float*       out  = (float*)d_out;

    __half *xh, *xth, *wqh, *wvh, *qh, *ph, *ah;
    float* s;
    cudaGetSymbolAddress((void**)&xh,  g_xh);
    cudaGetSymbolAddress((void**)&xth, g_xth);
    cudaGetSymbolAddress((void**)&wqh, g_wqh);
    cudaGetSymbolAddress((void**)&wvh, g_wvh);
    cudaGetSymbolAddress((void**)&qh,  g_qh);
    cudaGetSymbolAddress((void**)&s,   g_s);
    cudaGetSymbolAddress((void**)&ph,  g_ph);
    cudaGetSymbolAddress((void**)&ah,  g_ah);

    cudaFuncSetAttribute(mma_gemm_nt<0>, cudaFuncAttributeMaxDynamicSharedMemorySize, GEMM_SMEM);
    cudaFuncSetAttribute(mma_gemm_nt<1>, cudaFuncAttributeMaxDynamicSharedMemorySize, GEMM_SMEM);

    const long long sXD = (long long)SEQ * DIM;
    const long long sSS = (long long)SEQ * SEQ;
    const long long sTX = (long long)DIM * SEQ;

    // --- input preprocessing ---
    {
        const int nx4 = NB * SEQ * DIM / 4;
        convert_kernel<<<nx4 / 256, 256>>>(x, xh, nx4);
        const int nw4 = DIM * DIM / 4;
        convert_kernel<<<nw4 / 256, 256>>>(Wqk, wqh, nw4);
        convert_kernel<<<nw4 / 256, 256>>>(Wvc, wvh, nw4);
        transpose_h_kernel<<<dim3(DIM / 32, SEQ / 32, NB), 256>>>(x, xth);
    }

    // 1) q = xh · wqh^T -> fp16
    mma_gemm_nt<1><<<dim3(DIM / 128, (NB * SEQ) / 128, 1), 256, GEMM_SMEM>>>(
        xh, wqh, nullptr, qh, DIM, DIM, 0, 0, 0, 1.0f);

    // 2) S_b = qh_b · xh_b^T -> fp32
    mma_gemm_nt<0><<<dim3(SEQ / 128, SEQ / 128, NB), 256, GEMM_SMEM>>>(
        qh, xh, s, nullptr, DIM, SEQ, sXD, sXD, sSS, 1.0f);

    // 3) P = softmax(mask ? S/32 : -inf); write 1024*P fp16
    softmax_mask_h<<<NB * SEQ, 256>>>(s, mask, ph);

    // 4) 1024*att_b = ph_b · xth_b^T -> fp16 (keep 1024 factor)
    mma_gemm_nt<1><<<dim3(DIM / 128, SEQ / 128, NB), 256, GEMM_SMEM>>>(
        ph, xth, nullptr, ah, SEQ, DIM, sSS, sTX, sXD, 1.0f);

    // 5) out = (1024*att · wvh^T) / 1024 -> fp32
    mma_gemm_nt<0><<<dim3(DIM / 128, (NB * SEQ) / 128, 1), 256, GEMM_SMEM>>>(
        ah, wvh, out, nullptr, DIM, DIM, 0, 0, 0, 1.0f / 1024.0f);
}

// round 6
// speedup vs baseline: 7.7230x; 1.0665x over previous
#include <cuda_runtime.h>
#include <cuda_fp16.h>
#include <math.h>
#include <stdint.h>

// Problem constants: N=4, n=2048, d=1024
#define NB   4
#define SEQ  2048
#define DIM  1024

// ---------------------------------------------------------------------------
// Scratch (__device__ globals; allocation-free rule)
// ---------------------------------------------------------------------------
__device__ __half g_xh [(size_t)NB*SEQ*DIM];
__device__ __half g_xth[(size_t)NB*DIM*SEQ];   // x^T per batch [DIM,SEQ]
__device__ __half g_wqh[(size_t)DIM*DIM];
__device__ __half g_wvh[(size_t)DIM*DIM];
__device__ __half g_qh [(size_t)NB*SEQ*DIM];
__device__ __half g_sh [(size_t)NB*SEQ*SEQ];   // masked, scaled scores (fp16)
__device__ __half g_ph [(size_t)NB*SEQ*SEQ];   // 1024 * p
__device__ __half g_ah [(size_t)NB*SEQ*DIM];   // 1024 * att

// ---------------------------------------------------------------------------
// Baseline-PTX helpers (compute_100-safe)
// ---------------------------------------------------------------------------
__device__ __forceinline__ uint32_t smem_u32(const void* p) {
    uint32_t a;
    asm("{ .reg .u64 t; cvta.to.shared.u64 t, %1; cvt.u32.u64 %0, t; }" : "=r"(a) : "l"(p));
    return a;
}
__device__ __forceinline__ void ldsm4(uint32_t* r, uint32_t a) {
    asm volatile("ldmatrix.sync.aligned.m8n8.x4.shared.b16 {%0,%1,%2,%3}, [%4];"
        : "=r"(r[0]), "=r"(r[1]), "=r"(r[2]), "=r"(r[3]) : "r"(a));
}
__device__ __forceinline__ void mma16816(float* c, const uint32_t* a, const uint32_t* b) {
    asm volatile("mma.sync.aligned.m16n8k16.row.col.f32.f16.f16.f32 "
        "{%0,%1,%2,%3}, {%4,%5,%6,%7}, {%8,%9}, {%0,%1,%2,%3};"
        : "+f"(c[0]), "+f"(c[1]), "+f"(c[2]), "+f"(c[3])
        : "r"(a[0]), "r"(a[1]), "r"(a[2]), "r"(a[3]), "r"(b[0]), "r"(b[1]));
}
#define CP_ASYNC16(so, gp) \
    asm volatile("cp.async.cg.shared.global [%0], [%1], 16;" :: "r"(so), "l"(gp) : "memory")
#define CP_COMMIT() asm volatile("cp.async.commit_group;" ::: "memory")
#define CP_WAIT2()  asm volatile("cp.async.wait_group 2;" ::: "memory")

// SW64-style swizzle for 64B rows
#define SWZ64(o) ((o) ^ (((o) >> 3) & 0x30))

// ---------------------------------------------------------------------------
// fp16 NT GEMM: C[M,N] = A[M,K] · B[N,K]^T (fp32 accum)
// MODE 0: fp32 C * escale.  MODE 1: fp16 C * escale.
// MODE 2: fp16 masked score: mask ? C*escale : -65504.
// 128x128 CTA tile, 128 threads (2x2 warps of 64x64), BK=32, 4-stage
// cp.async pipeline, 2 CTAs/SM.
// ---------------------------------------------------------------------------
#define TILE_B  8192            // 128 rows x 64 bytes
#define STAGE_B 16384           // A, B tiles
#define NSTAGE  4
#define GEMM_SMEM (NSTAGE * STAGE_B)

template <int MODE>
__global__ __launch_bounds__(128, 2)
void mma_gemm_nt(const __half* __restrict__ Ah, const __half* __restrict__ Bh,
                 float* __restrict__ Cf, __half* __restrict__ Ch,
                 const int* __restrict__ Mask,
                 int K, int ldc, long long sA, long long sB, long long sC, float escale)
{
    extern __shared__ char smraw[];
    const uint32_t base = smem_u32(smraw);

    const int tid  = threadIdx.x;
    const int wid  = tid >> 5;
    const int lid  = tid & 31;
    const int bz   = blockIdx.z;
    const int row0 = blockIdx.y * 128;
    const int col0 = blockIdx.x * 128;

    const int warp_m = wid >> 1;          // 0..1 -> 64-row slab
    const int warp_n = wid & 1;           // 0..1 -> 64-col slab

    const __half* src[2] = { Ah + (size_t)bz * sA, Bh + (size_t)bz * sB };
    const int rb[2] = { row0, col0 };

    const int nCh = K >> 5;               // chunks of 32

    // loader: 1024 x 16B copies; id = tid + g*128 -> tile(2) x row(128) x c16(4)
    auto issue_stage = [&](int i) {
        const uint32_t stage = base + (uint32_t)(i & 3) * STAGE_B;
        const int k0 = i << 5;
        #pragma unroll
        for (int g = 0; g < 8; g++) {
            const int id   = tid + g * 128;
            const int tile = id >> 9;
            const int rem  = id & 511;
            const int r    = rem >> 2;
            const int c16  = rem & 3;
            const __half* gp = src[tile] + (size_t)(rb[tile] + r) * K + k0 + c16 * 8;
            const uint32_t so = stage + (uint32_t)tile * TILE_B + SWZ64(r * 64 + c16 * 16);
            CP_ASYNC16(so, gp);
        }
    };

    float acc[4][8][4];
    #pragma unroll
    for (int mt = 0; mt < 4; mt++)
        #pragma unroll
        for (int nt = 0; nt < 8; nt++)
            #pragma unroll
            for (int e = 0; e < 4; e++) acc[mt][nt][e] = 0.f;

    issue_stage(0); CP_COMMIT();
    issue_stage(1); CP_COMMIT();
    issue_stage(2); CP_COMMIT();

    // ldmatrix lane addressing
    const int a_r_lane = ((lid >> 3) & 1) * 8 + (lid & 7);
    const int a_c_lane = lid >> 4;
    const int b_r_lane = (lid >> 4) * 8 + (lid & 7);
    const int b_c_lane = (lid >> 3) & 1;

    for (int i = 0; i < nCh; i++) {
        CP_WAIT2();
        __syncthreads();                 // stage i visible; stage (i-1) reads done
        if (i + 3 < nCh) issue_stage(i + 3);
        CP_COMMIT();

        const uint32_t stage = base + (uint32_t)(i & 3) * STAGE_B;
        const uint32_t sA = stage;
        const uint32_t sB = stage + TILE_B;

        #pragma unroll
        for (int s = 0; s < 2; s++) {    // two k16 steps per 32-chunk
            uint32_t af[4][4], bf[4][4];
            #pragma unroll
            for (int mt = 0; mt < 4; mt++) {
                const int row = warp_m * 64 + mt * 16 + a_r_lane;
                const int off = SWZ64(row * 64 + (2 * s + a_c_lane) * 16);
                ldsm4(af[mt], sA + off);
            }
            #pragma unroll
            for (int nt = 0; nt < 4; nt++) {
                const int row = warp_n * 64 + nt * 16 + b_r_lane;
                const int off = SWZ64(row * 64 + (2 * s + b_c_lane) * 16);
                ldsm4(bf[nt], sB + off);
            }
            #pragma unroll
            for (int mt = 0; mt < 4; mt++)
                #pragma unroll
                for (int nt = 0; nt < 8; nt++)
                    mma16816(acc[mt][nt], af[mt], &bf[nt >> 1][(nt & 1) * 2]);
        }
    }

    // Epilogue
    const int er = lid >> 2;
    const int ec = (lid & 3) * 2;
    #pragma unroll
    for (int mt = 0; mt < 4; mt++) {
        #pragma unroll
        for (int nt = 0; nt < 8; nt++) {
            const int r_g = row0 + warp_m * 64 + mt * 16 + er;
            const int c_g = col0 + warp_n * 64 + nt * 8 + ec;
            const size_t o0 = (size_t)bz * sC + (size_t)r_g * ldc + c_g;
            const size_t o1 = o0 + (size_t)8 * ldc;
            if (MODE == 0) {
                Cf[o0]     = acc[mt][nt][0] * escale;
                Cf[o0 + 1] = acc[mt][nt][1] * escale;
                Cf[o1]     = acc[mt][nt][2] * escale;
                Cf[o1 + 1] = acc[mt][nt][3] * escale;
            } else if (MODE == 1) {
                __half2 h0, h1;
                h0.x = __float2half(acc[mt][nt][0] * escale);
                h0.y = __float2half(acc[mt][nt][1] * escale);
                h1.x = __float2half(acc[mt][nt][2] * escale);
                h1.y = __float2half(acc[mt][nt][3] * escale);
                *(__half2*)(Ch + o0) = h0;
                *(__half2*)(Ch + o1) = h1;
            } else {
                const size_t mrow0 = ((size_t)bz * SEQ + r_g) * SEQ + c_g;
                const size_t mrow1 = mrow0 + (size_t)8 * SEQ;
                const int2 m0 = *(const int2*)(Mask + mrow0);
                const int2 m1 = *(const int2*)(Mask + mrow1);
                __half2 h0, h1;
                h0.x = m0.x ? __float2half(acc[mt][nt][0] * escale) : __float2half(-65504.f);
                h0.y = m0.y ? __float2half(acc[mt][nt][1] * escale) : __float2half(-65504.f);
                h1.x = m1.x ? __float2half(acc[mt][nt][2] * escale) : __float2half(-65504.f);
                h1.y = m1.y ? __float2half(acc[mt][nt][3] * escale) : __float2half(-65504.f);
                *(__half2*)(Ch + o0) = h0;
                *(__half2*)(Ch + o1) = h1;
            }
        }
    }
}

// ---------------------------------------------------------------------------
// fp32 -> fp16 convert (weights)
// ---------------------------------------------------------------------------
__global__ __launch_bounds__(256)
void convert_kernel(const float* __restrict__ s, __half* __restrict__ h, int n4)
{
    const int i = blockIdx.x * blockDim.x + threadIdx.x;
    if (i >= n4) return;
    const float4 v = ((const float4*)s)[i];
    __half2 a, b;
    a.x = __float2half(v.x); a.y = __float2half(v.y);
    b.x = __float2half(v.z); b.y = __float2half(v.w);
    *(__half2*)(h + (size_t)i * 4)     = a;
    *(__half2*)(h + (size_t)i * 4 + 2) = b;
}

// ---------------------------------------------------------------------------
// x [NB,SEQ,DIM] -> xh fp16 AND xth fp16 [NB,DIM,SEQ] in one pass
// ---------------------------------------------------------------------------
__global__ __launch_bounds__(256)
void prep_x_kernel(const float* __restrict__ x, __half* __restrict__ xh,
                   __half* __restrict__ xth)
{
    __shared__ float t[32][33];
    const int b  = blockIdx.z;
    const int d0 = blockIdx.x * 32;
    const int k0 = blockIdx.y * 32;
    const int tx = threadIdx.x & 31;
    const int ty = threadIdx.x >> 5;
    #pragma unroll
    for (int j = 0; j < 32; j += 8) {
        const float v = x[(size_t)b * SEQ * DIM + (size_t)(k0 + ty + j) * DIM + d0 + tx];
        t[ty + j][tx] = v;
        xh[(size_t)b * SEQ * DIM + (size_t)(k0 + ty + j) * DIM + d0 + tx] = __float2half(v);
    }
    __syncthreads();
    #pragma unroll
    for (int j = 0; j < 32; j += 8) {
        const size_t off = (size_t)b * DIM * SEQ + (size_t)(d0 + ty + j) * SEQ + k0 + tx;
        xth[off] = __float2half(t[tx][ty + j]);
    }
}

// ---------------------------------------------------------------------------
// softmax over fp16 masked scores; outputs fp16 of (1024 * p)
// ---------------------------------------------------------------------------
__global__ __launch_bounds__(256)
void softmax_h(const __half* __restrict__ Sh, __half* __restrict__ Ph)
{
    const size_t row = blockIdx.x;
    const __half* s  = Sh + row * SEQ;
    const int    tid = threadIdx.x;

    float v[8];
    {   // 8 halves per thread via one 16B load
        const int b = tid * 8;
        const uint4 raw = *(const uint4*)(s + b);
        const __half2* hp = (const __half2*)&raw;
        #pragma unroll
        for (int u = 0; u < 4; u++) {
            const float2 f = __half22float2(hp[u]);
            v[u * 2]     = f.x;
            v[u * 2 + 1] = f.y;
        }
    }

    __shared__ float red[8];
    float mx = v[0];
    #pragma unroll
    for (int i = 1; i < 8; i++) mx = fmaxf(mx, v[i]);
    #pragma unroll
    for (int o = 16; o > 0; o >>= 1) mx = fmaxf(mx, __shfl_xor_sync(0xffffffffu, mx, o));
    if ((tid & 31) == 0) red[tid >> 5] = mx;
    __syncthreads();
    mx = red[0];
    #pragma unroll
    for (int w = 1; w < 8; w++) mx = fmaxf(mx, red[w]);
    __syncthreads();

    float sum = 0.f;
    #pragma unroll
    for (int i = 0; i < 8; i++) { v[i] = expf(v[i] - mx); sum += v[i]; }
    #pragma unroll
    for (int o = 16; o > 0; o >>= 1) sum += __shfl_xor_sync(0xffffffffu, sum, o);
    if ((tid & 31) == 0) red[tid >> 5] = sum;
    __syncthreads();
    sum = red[0];
    #pragma unroll
    for (int w = 1; w < 8; w++) sum += red[w];

    const float inv = 1024.0f / sum;     // scale probs by 1024 (exact pow2)
    {
        const int b = tid * 8;
        uint4 outw;
        __half2* hp = (__half2*)&outw;
        #pragma unroll
        for (int u = 0; u < 4; u++) {
            hp[u].x = __float2half(v[u * 2]     * inv);
            hp[u].y = __float2half(v[u * 2 + 1] * inv);
        }
        *(uint4*)(Ph + row * SEQ + b) = outw;
    }
}

// ---------------------------------------------------------------------------
extern "C" void kernel_launch(void* const* d_in, const int* in_sizes, int n_in,
                              void* d_out, int out_size)
{
    const float* x    = (const float*)d_in[0];
    const int*   mask = (const int*)  d_in[1];
    const float* Wqk  = (const float*)d_in[2];
    const float* Wvc  = (const float*)d_in[3];
    float*       out  = (float*)d_out;

    __half *xh, *xth, *wqh, *wvh, *qh, *sh, *ph, *ah;
    cudaGetSymbolAddress((void**)&xh,  g_xh);
    cudaGetSymbolAddress((void**)&xth, g_xth);
    cudaGetSymbolAddress((void**)&wqh, g_wqh);
    cudaGetSymbolAddress((void**)&wvh, g_wvh);
    cudaGetSymbolAddress((void**)&qh,  g_qh);
    cudaGetSymbolAddress((void**)&sh,  g_sh);
    cudaGetSymbolAddress((void**)&ph,  g_ph);
    cudaGetSymbolAddress((void**)&ah,  g_ah);

    cudaFuncSetAttribute(mma_gemm_nt<0>, cudaFuncAttributeMaxDynamicSharedMemorySize, GEMM_SMEM);
    cudaFuncSetAttribute(mma_gemm_nt<1>, cudaFuncAttributeMaxDynamicSharedMemorySize, GEMM_SMEM);
    cudaFuncSetAttribute(mma_gemm_nt<2>, cudaFuncAttributeMaxDynamicSharedMemorySize, GEMM_SMEM);

    const long long sXD = (long long)SEQ * DIM;
    const long long sSS = (long long)SEQ * SEQ;
    const long long sTX = (long long)DIM * SEQ;

    // --- input preprocessing ---
    {
        prep_x_kernel<<<dim3(DIM / 32, SEQ / 32, NB), 256>>>(x, xh, xth);
        const int nw4 = DIM * DIM / 4;
        convert_kernel<<<nw4 / 256, 256>>>(Wqk, wqh, nw4);
        convert_kernel<<<nw4 / 256, 256>>>(Wvc, wvh, nw4);
    }

    // 1) q = xh · wqh^T -> fp16
    mma_gemm_nt<1><<<dim3(DIM / 128, (NB * SEQ) / 128, 1), 128, GEMM_SMEM>>>(
        xh, wqh, nullptr, qh, nullptr, DIM, DIM, 0, 0, 0, 1.0f);

    // 2) Sh_b = mask ? (qh_b · xh_b^T)/32 : -65504  -> fp16
    mma_gemm_nt<2><<<dim3(SEQ / 128, SEQ / 128, NB), 128, GEMM_SMEM>>>(
        qh, xh, nullptr, sh, mask, DIM, SEQ, sXD, sXD, sSS, 0.03125f);

    // 3) P = softmax(Sh); write 1024*P fp16
    softmax_h<<<NB * SEQ, 256>>>(sh, ph);

    // 4) 1024*att_b = ph_b · xth_b^T -> fp16 (keep 1024 factor)
    mma_gemm_nt<1><<<dim3(DIM / 128, SEQ / 128, NB), 128, GEMM_SMEM>>>(
        ph, xth, nullptr, ah, nullptr, SEQ, DIM, sSS, sTX, sXD, 1.0f);

    // 5) out = (1024*att · wvh^T) / 1024 -> fp32
    mma_gemm_nt<0><<<dim3(DIM / 128, (NB * SEQ) / 128, 1), 128, GEMM_SMEM>>>(
        ah, wvh, out, nullptr, nullptr, DIM, DIM, 0, 0, 0, 1.0f / 1024.0f);
}